// round 14
// baseline (speedup 1.0000x reference)
#include <cuda_runtime.h>
#include <cuda_fp16.h>
#include <cstdint>

#define TOKS 7
#define THREADS 256
#define HSTR 72           // half stride for T0 rows (144B, conflict-free)
#define YSTR 68           // float stride for Yf

// smem byte offsets
#define T0_OFF   0                  // 128 x HSTR half  (A1 tile)   18432
#define YF_OFF   18432              // 128 x YSTR float (Y tile)    34816
#define B2F_OFF  53248              // 4ks x 8nt x 32 x uint2 = 8192
#define B3F_OFF  61440              // 4ks x 4nt x 32 x uint2 = 4096
#define B2S_OFF  65536              // 64 floats = 256
#define XS_OFF   65792              // 8 warps x 17 float2 = 1088
#define SMEM_BYTES 66880            // x3 = 200640 <= 228KB -> 3 CTAs/SM

__device__ __forceinline__ void mma16(float c[4], const uint32_t a[4], uint32_t b0, uint32_t b1) {
    asm volatile(
        "mma.sync.aligned.m16n8k16.row.col.f32.f16.f16.f32 "
        "{%0,%1,%2,%3}, {%4,%5,%6,%7}, {%8,%9}, {%0,%1,%2,%3};"
        : "+f"(c[0]), "+f"(c[1]), "+f"(c[2]), "+f"(c[3])
        : "r"(a[0]), "r"(a[1]), "r"(a[2]), "r"(a[3]), "r"(b0), "r"(b1));
}

__device__ __forceinline__ uint32_t h2pack(float a, float b) {
    __half2 h = __floats2half2_rn(a, b);
    return *(uint32_t*)&h;
}

// unrolled skeleton aggregation (adj + I, all-ones)
__device__ __forceinline__ void aggF(const float* s, float* g) {
    g[0]  = s[0] + s[1] + s[2] + s[5] + s[6];
    g[1]  = s[1] + s[0] + s[3];
    g[2]  = s[2] + s[0] + s[4];
    g[3]  = s[3] + s[1];
    g[4]  = s[4] + s[2];
    g[5]  = s[5] + s[0] + s[7] + s[11];
    g[6]  = s[6] + s[0] + s[8] + s[12];
    g[7]  = s[7] + s[5] + s[9];
    g[8]  = s[8] + s[6] + s[10];
    g[9]  = s[9] + s[7];
    g[10] = s[10] + s[8];
    g[11] = s[11] + s[5] + s[13];
    g[12] = s[12] + s[6] + s[14];
    g[13] = s[13] + s[11] + s[15];
    g[14] = s[14] + s[12] + s[16];
    g[15] = s[15] + s[13];
    g[16] = s[16] + s[14];
}

extern __shared__ char smem[];

__global__ void __launch_bounds__(THREADS, 3)
sge_h(const float* __restrict__ x,
      const float* __restrict__ W1, const float* __restrict__ b1,
      const float* __restrict__ W2, const float* __restrict__ b2,
      const float* __restrict__ W3, const float* __restrict__ b3,
      float* __restrict__ out, int NT, int nstages)
{
    const int tid = threadIdx.x;
    const int warp = tid >> 5, lane = tid & 31;
    const int g = lane >> 2, q = lane & 3;
    const int r0 = warp * 16 + g;              // warp tile rows (r0, r0+8)

    __half* T0 = (__half*)(smem + T0_OFF);
    float*  Yf = (float*)(smem + YF_OFF);
    uint2*  B2f = (uint2*)(smem + B2F_OFF);
    uint2*  B3f = (uint2*)(smem + B3F_OFF);
    float*  b2s = (float*)(smem + B2S_OFF);
    float2* xsw = (float2*)(smem + XS_OFF) + warp * 17;

    // ---- init: pack W2/W3 into per-lane m16n8k16 fp16 B fragments ----
    for (int idx = tid; idx < 4 * 8 * 32; idx += THREADS) {
        int l = idx & 31, nt = (idx >> 5) & 7, ks = idx >> 8;
        int gg = l >> 2, qq = l & 3, n = nt * 8 + gg, k0 = ks * 16 + 2 * qq;
        uint2 v;
        v.x = h2pack(W2[k0 * 64 + n],       W2[(k0 + 1) * 64 + n]);
        v.y = h2pack(W2[(k0 + 8) * 64 + n], W2[(k0 + 9) * 64 + n]);
        B2f[idx] = v;
    }
    for (int idx = tid; idx < 4 * 4 * 32; idx += THREADS) {
        int l = idx & 31, nt = (idx >> 5) & 3, ks = idx >> 7;
        int gg = l >> 2, qq = l & 3, n = nt * 8 + gg, k0 = ks * 16 + 2 * qq;
        uint2 v;
        v.x = h2pack(W3[k0 * 32 + n],       W3[(k0 + 1) * 32 + n]);
        v.y = h2pack(W3[(k0 + 8) * 32 + n], W3[(k0 + 9) * 32 + n]);
        B3f[idx] = v;
    }
    for (int i = tid; i < 64; i += THREADS) b2s[i] = b2[i];
    for (int i = tid; i < (128 * HSTR) / 2; i += THREADS)
        ((uint32_t*)T0)[i] = 0u;   // zero T0, pad rows 119..127 stay 0

    // per-lane layer-1 weights/biases for features {2*lane, 2*lane+1}
    const float wA0 = __ldg(W1 + 2 * lane),     wA1 = __ldg(W1 + 64 + 2 * lane);
    const float wB0 = __ldg(W1 + 2 * lane + 1), wB1 = __ldg(W1 + 64 + 2 * lane + 1);
    const float bA  = __ldg(b1 + 2 * lane),     bB  = __ldg(b1 + 2 * lane + 1);
    const float b3r = __ldg(b3 + lane);

    // ---- initial x prefetch (warp w owns token w of its stage) ----
    float2 xcur = make_float2(0.f, 0.f);
    {
        int t0 = blockIdx.x * TOKS + warp;
        if (warp < TOKS && lane < 17 && t0 < NT)
            xcur = __ldg((const float2*)x + (size_t)t0 * 17 + lane);
    }
    __syncthreads();

    int ptok0 = 0, pvtok = 0;   // previous stage pending Y

    for (int s = blockIdx.x; s < nstages; s += gridDim.x) {
        const int tok0 = s * TOKS;
        const int vtok = min(TOKS, NT - tok0);

        // ---- stage x, prefetch next ----
        if (warp < TOKS && lane < 17) xsw[lane] = xcur;
        {
            int ns = s + gridDim.x;
            int tn = ns * TOKS + warp;
            xcur = make_float2(0.f, 0.f);
            if (warp < TOKS && lane < 17 && ns < nstages && tn < NT)
                xcur = __ldg((const float2*)x + (size_t)tn * 17 + lane);
        }
        __syncwarp();

        // ---- phase A1: layer 1 + agg (warp-local) -> T0 (fp16, split stores) ----
        if (warp < vtok) {
            float gx[17], gy[17];
            {
                float xax[17], xay[17];
                #pragma unroll
                for (int j = 0; j < 17; j++) { float2 v = xsw[j]; xax[j] = v.x; xay[j] = v.y; }
                aggF(xax, gx); aggF(xay, gy);
            }
            __half* au = T0 + (17 * warp) * HSTR + 2 * lane;
            {
                float h[17], ga[17];
                #pragma unroll
                for (int j = 0; j < 17; j++)
                    h[j] = fmaxf(fmaf(gx[j], wA0, fmaf(gy[j], wA1, bA)), 0.f);
                aggF(h, ga);
                #pragma unroll
                for (int j = 0; j < 17; j++) au[j * HSTR] = __float2half_rn(ga[j]);
            }
            {
                float h[17], gb[17];
                #pragma unroll
                for (int j = 0; j < 17; j++)
                    h[j] = fmaxf(fmaf(gx[j], wB0, fmaf(gy[j], wB1, bB)), 0.f);
                aggF(h, gb);
                #pragma unroll
                for (int j = 0; j < 17; j++) au[j * HSTR + 1] = __float2half_rn(gb[j]);
            }
        }

        // ---- phase A2: out = agg(prev Y) + b3 -> gmem ----
        if (warp < pvtok) {
            const float* yc = Yf + (warp * 17) * YSTR + lane;
            float y[17];
            #pragma unroll
            for (int j = 0; j < 17; j++) y[j] = yc[j * YSTR];
            float o[17];
            aggF(y, o);
            float* ob = out + ((size_t)(ptok0 + warp) * 17) * 32 + lane;
            #pragma unroll
            for (int j = 0; j < 17; j++) ob[j * 32] = o[j] + b3r;
        }
        __syncthreads();   // T0 ready, prev Y consumed

        // ---- phase B: GEMM1 in two N-halves -> regs -> GEMM2 -> Yf ----
        {
            uint32_t a2[4][4];    // GEMM2 A-fragments (h2 in registers)
            const __half* ar = T0 + r0 * HSTR;

            #pragma unroll
            for (int half = 0; half < 2; half++) {
                float c1[4][4];
                #pragma unroll
                for (int nt = 0; nt < 4; nt++)
                    #pragma unroll
                    for (int i = 0; i < 4; i++) c1[nt][i] = 0.f;

                #pragma unroll
                for (int ks = 0; ks < 4; ks++) {
                    const int k0 = ks * 16 + 2 * q;
                    uint32_t a[4];
                    a[0] = *(const uint32_t*)(ar + k0);
                    a[1] = *(const uint32_t*)(ar + 8 * HSTR + k0);
                    a[2] = *(const uint32_t*)(ar + k0 + 8);
                    a[3] = *(const uint32_t*)(ar + 8 * HSTR + k0 + 8);
                    const uint2* bf = B2f + ks * 256 + half * 128 + lane;
                    #pragma unroll
                    for (int nt = 0; nt < 4; nt++) {
                        uint2 b = bf[nt * 32];
                        mma16(c1[nt], a, b.x, b.y);
                    }
                }
                // bias + relu + pack: C-frags (2 adjacent n8 tiles) == A-frag of one k16 tile
                #pragma unroll
                for (int kt = 0; kt < 2; kt++) {
                    const int ktg = half * 2 + kt;
                    const int cb = ktg * 16 + 2 * q;
                    const float bl0 = b2s[cb],     bl1 = b2s[cb + 1];
                    const float bh0 = b2s[cb + 8], bh1 = b2s[cb + 9];
                    a2[ktg][0] = h2pack(fmaxf(c1[2 * kt][0] + bl0, 0.f),
                                        fmaxf(c1[2 * kt][1] + bl1, 0.f));
                    a2[ktg][1] = h2pack(fmaxf(c1[2 * kt][2] + bl0, 0.f),
                                        fmaxf(c1[2 * kt][3] + bl1, 0.f));
                    a2[ktg][2] = h2pack(fmaxf(c1[2 * kt + 1][0] + bh0, 0.f),
                                        fmaxf(c1[2 * kt + 1][1] + bh1, 0.f));
                    a2[ktg][3] = h2pack(fmaxf(c1[2 * kt + 1][2] + bh0, 0.f),
                                        fmaxf(c1[2 * kt + 1][3] + bh1, 0.f));
                }
            }

            // GEMM2: Y = h2 @ W3 (N=32), A-frags straight from registers
            float c2[4][4];
            #pragma unroll
            for (int nt = 0; nt < 4; nt++)
                #pragma unroll
                for (int i = 0; i < 4; i++) c2[nt][i] = 0.f;

            #pragma unroll
            for (int kt = 0; kt < 4; kt++) {
                const uint2* bf = B3f + kt * 128 + lane;
                #pragma unroll
                for (int nt = 0; nt < 4; nt++) {
                    uint2 b = bf[nt * 32];
                    mma16(c2[nt], a2[kt], b.x, b.y);
                }
            }
            #pragma unroll
            for (int nt = 0; nt < 4; nt++) {
                int cb = nt * 8 + 2 * q;
                *(float2*)(Yf + r0 * YSTR + cb) = make_float2(c2[nt][0], c2[nt][1]);
                *(float2*)(Yf + (r0 + 8) * YSTR + cb) = make_float2(c2[nt][2], c2[nt][3]);
            }
        }
        ptok0 = tok0; pvtok = vtok;
        __syncthreads();   // Y ready; T0 free for next stage
    }

    // ---- tail: flush last stage's Y ----
    if (warp < pvtok) {
        const float* yc = Yf + (warp * 17) * YSTR + lane;
        float y[17];
        #pragma unroll
        for (int j = 0; j < 17; j++) y[j] = yc[j * YSTR];
        float o[17];
        aggF(y, o);
        float* ob = out + ((size_t)(ptok0 + warp) * 17) * 32 + lane;
        #pragma unroll
        for (int j = 0; j < 17; j++) ob[j * 32] = o[j] + b3r;
    }
}

extern "C" void kernel_launch(void* const* d_in, const int* in_sizes, int n_in,
                              void* d_out, int out_size) {
    const float* x  = (const float*)d_in[0];
    const float* W1 = (const float*)d_in[1];
    const float* b1 = (const float*)d_in[2];
    const float* W2 = (const float*)d_in[3];
    const float* b2 = (const float*)d_in[4];
    const float* W3 = (const float*)d_in[5];
    const float* b3 = (const float*)d_in[6];
    float* out = (float*)d_out;

    const int NT = in_sizes[0] / (17 * 2);          // 65536 tokens
    const int nstages = (NT + TOKS - 1) / TOKS;     // 9363

    static int attr_done = 0;
    if (!attr_done) {
        cudaFuncSetAttribute(sge_h, cudaFuncAttributeMaxDynamicSharedMemorySize, SMEM_BYTES);
        attr_done = 1;
    }
    int grid = nstages < 444 ? nstages : 444;       // 3 CTAs x 148 SMs
    sge_h<<<grid, THREADS, SMEM_BYTES>>>(x, W1, b1, W2, b2, W3, b3, out, NT, nstages);
}

// round 15
// speedup vs baseline: 1.1297x; 1.1297x over previous
#include <cuda_runtime.h>
#include <cuda_fp16.h>
#include <cstdint>

#define TOKS 15
#define THREADS 256
#define HSTR 72           // half stride for T0 rows (144B, conflict-free)
#define YSTR 36           // float stride for Yf (32 cols + pad)

// smem byte offsets
#define T0_OFF   0                  // 256 x HSTR half  (A1 tile)   36864
#define YF_OFF   36864              // 256 x YSTR float (Y tile)    36864
#define B2F_OFF  73728              // 4ks x 8nt x 32 x uint2 = 8192
#define B3F_OFF  81920              // 4kt x 4nt x 32 x uint2 = 4096
#define B2S_OFF  86016              // 64 floats = 256
#define XS_OFF   86272              // 15 tokens x 17 float2 = 2040
#define SMEM_BYTES 88320            // x2 = 176640 <= 228KB -> 2 CTAs/SM

__device__ __forceinline__ void mma16(float c[4], const uint32_t a[4], uint32_t b0, uint32_t b1) {
    asm volatile(
        "mma.sync.aligned.m16n8k16.row.col.f32.f16.f16.f32 "
        "{%0,%1,%2,%3}, {%4,%5,%6,%7}, {%8,%9}, {%0,%1,%2,%3};"
        : "+f"(c[0]), "+f"(c[1]), "+f"(c[2]), "+f"(c[3])
        : "r"(a[0]), "r"(a[1]), "r"(a[2]), "r"(a[3]), "r"(b0), "r"(b1));
}

__device__ __forceinline__ uint32_t h2pack(float a, float b) {
    __half2 h = __floats2half2_rn(a, b);
    return *(uint32_t*)&h;
}

// unrolled skeleton aggregation (adj + I, all-ones)
__device__ __forceinline__ void aggF(const float* s, float* g) {
    g[0]  = s[0] + s[1] + s[2] + s[5] + s[6];
    g[1]  = s[1] + s[0] + s[3];
    g[2]  = s[2] + s[0] + s[4];
    g[3]  = s[3] + s[1];
    g[4]  = s[4] + s[2];
    g[5]  = s[5] + s[0] + s[7] + s[11];
    g[6]  = s[6] + s[0] + s[8] + s[12];
    g[7]  = s[7] + s[5] + s[9];
    g[8]  = s[8] + s[6] + s[10];
    g[9]  = s[9] + s[7];
    g[10] = s[10] + s[8];
    g[11] = s[11] + s[5] + s[13];
    g[12] = s[12] + s[6] + s[14];
    g[13] = s[13] + s[11] + s[15];
    g[14] = s[14] + s[12] + s[16];
    g[15] = s[15] + s[13];
    g[16] = s[16] + s[14];
}

extern __shared__ char smem[];

__global__ void __launch_bounds__(THREADS, 2)
sge_h(const float* __restrict__ x,
      const float* __restrict__ W1, const float* __restrict__ b1,
      const float* __restrict__ W2, const float* __restrict__ b2,
      const float* __restrict__ W3, const float* __restrict__ b3,
      float* __restrict__ out, int NT, int nstages)
{
    const int tid = threadIdx.x;
    const int warp = tid >> 5, lane = tid & 31;
    const int g = lane >> 2, q = lane & 3;

    __half* T0 = (__half*)(smem + T0_OFF);
    float*  Yf = (float*)(smem + YF_OFF);
    uint2*  B2f = (uint2*)(smem + B2F_OFF);
    uint2*  B3f = (uint2*)(smem + B3F_OFF);
    float*  b2s = (float*)(smem + B2S_OFF);
    float2* xs = (float2*)(smem + XS_OFF);

    // ---- init: pack W2/W3 into per-lane m16n8k16 fp16 B fragments ----
    for (int idx = tid; idx < 4 * 8 * 32; idx += THREADS) {
        int l = idx & 31, nt = (idx >> 5) & 7, ks = idx >> 8;
        int gg = l >> 2, qq = l & 3, n = nt * 8 + gg, k0 = ks * 16 + 2 * qq;
        uint2 v;
        v.x = h2pack(W2[k0 * 64 + n],       W2[(k0 + 1) * 64 + n]);
        v.y = h2pack(W2[(k0 + 8) * 64 + n], W2[(k0 + 9) * 64 + n]);
        B2f[idx] = v;
    }
    for (int idx = tid; idx < 4 * 4 * 32; idx += THREADS) {
        int l = idx & 31, nt = (idx >> 5) & 3, ks = idx >> 7;
        int gg = l >> 2, qq = l & 3, n = nt * 8 + gg, k0 = ks * 16 + 2 * qq;
        uint2 v;
        v.x = h2pack(W3[k0 * 32 + n],       W3[(k0 + 1) * 32 + n]);
        v.y = h2pack(W3[(k0 + 8) * 32 + n], W3[(k0 + 9) * 32 + n]);
        B3f[idx] = v;
    }
    for (int i = tid; i < 64; i += THREADS) b2s[i] = b2[i];
    for (int i = tid; i < (256 * HSTR) / 2; i += THREADS)
        ((uint32_t*)T0)[i] = 0u;   // zero T0, pad row 255 stays 0

    // per-lane layer-1 weights/biases for features {2*lane, 2*lane+1}
    const float wA0 = __ldg(W1 + 2 * lane),     wA1 = __ldg(W1 + 64 + 2 * lane);
    const float wB0 = __ldg(W1 + 2 * lane + 1), wB1 = __ldg(W1 + 64 + 2 * lane + 1);
    const float bA  = __ldg(b1 + 2 * lane),     bB  = __ldg(b1 + 2 * lane + 1);
    const float b3r = __ldg(b3 + lane);

    // ---- initial x prefetch: warp handles tokens {warp, warp+8} ----
    float2 xc[2];
    #pragma unroll
    for (int ti = 0; ti < 2; ti++) {
        int tt = warp + ti * 8;
        int tg = blockIdx.x * TOKS + tt;
        xc[ti] = make_float2(0.f, 0.f);
        if (tt < TOKS && lane < 17 && tg < NT)
            xc[ti] = __ldg((const float2*)x + (size_t)tg * 17 + lane);
    }
    __syncthreads();

    int ptok0 = 0, pvtok = 0;   // previous stage pending Y

    for (int s = blockIdx.x; s < nstages; s += gridDim.x) {
        const int tok0 = s * TOKS;
        const int vtok = min(TOKS, NT - tok0);

        // ---- stage x, prefetch next ----
        #pragma unroll
        for (int ti = 0; ti < 2; ti++) {
            int tt = warp + ti * 8;
            if (tt < TOKS && lane < 17) xs[tt * 17 + lane] = xc[ti];
        }
        {
            int ns = s + gridDim.x;
            #pragma unroll
            for (int ti = 0; ti < 2; ti++) {
                int tt = warp + ti * 8;
                int tg = ns * TOKS + tt;
                xc[ti] = make_float2(0.f, 0.f);
                if (tt < TOKS && lane < 17 && ns < nstages && tg < NT)
                    xc[ti] = __ldg((const float2*)x + (size_t)tg * 17 + lane);
            }
        }
        __syncwarp();

        // ---- phase A1: layer 1 + agg (warp-local, 2 tokens) -> T0 (fp16) ----
        #pragma unroll 1
        for (int ti = 0; ti < 2; ti++) {
            int t = warp + ti * 8;
            if (t < vtok) {
                const float2* xb = xs + t * 17;
                float gx[17], gy[17];
                {
                    float xax[17], xay[17];
                    #pragma unroll
                    for (int j = 0; j < 17; j++) { float2 v = xb[j]; xax[j] = v.x; xay[j] = v.y; }
                    aggF(xax, gx); aggF(xay, gy);
                }
                __half* au = T0 + (17 * t) * HSTR + 2 * lane;
                {
                    float h[17], ga[17];
                    #pragma unroll
                    for (int j = 0; j < 17; j++)
                        h[j] = fmaxf(fmaf(gx[j], wA0, fmaf(gy[j], wA1, bA)), 0.f);
                    aggF(h, ga);
                    #pragma unroll
                    for (int j = 0; j < 17; j++) au[j * HSTR] = __float2half_rn(ga[j]);
                }
                {
                    float h[17], gb[17];
                    #pragma unroll
                    for (int j = 0; j < 17; j++)
                        h[j] = fmaxf(fmaf(gx[j], wB0, fmaf(gy[j], wB1, bB)), 0.f);
                    aggF(h, gb);
                    #pragma unroll
                    for (int j = 0; j < 17; j++) au[j * HSTR + 1] = __float2half_rn(gb[j]);
                }
            }
        }

        // ---- phase A2: out = agg(prev Y) + b3 -> gmem (2 tokens) ----
        #pragma unroll 1
        for (int ti = 0; ti < 2; ti++) {
            int t = warp + ti * 8;
            if (t < pvtok) {
                const float* yc = Yf + (t * 17) * YSTR + lane;
                float y[17];
                #pragma unroll
                for (int j = 0; j < 17; j++) y[j] = yc[j * YSTR];
                float o[17];
                aggF(y, o);
                float* ob = out + ((size_t)(ptok0 + t) * 17) * 32 + lane;
                #pragma unroll
                for (int j = 0; j < 17; j++) ob[j * 32] = o[j] + b3r;
            }
        }
        __syncthreads();   // T0 ready, prev Y consumed

        // ---- phase B: dual m-tile, B-frags shared across both tiles ----
        {
            const int rA = warp * 16 + g;            // m-tile `warp`
            const int rB = (warp + 8) * 16 + g;      // m-tile `warp+8`
            const __half* arA = T0 + rA * HSTR;
            const __half* arB = T0 + rB * HSTR;

            uint32_t a2[2][4][4];   // h2 A-frags for both m-tiles

            // GEMM1 in two N-halves; each B-frag load feeds both m-tiles
            #pragma unroll
            for (int half = 0; half < 2; half++) {
                float c1[2][4][4];
                #pragma unroll
                for (int m = 0; m < 2; m++)
                    #pragma unroll
                    for (int nt = 0; nt < 4; nt++)
                        #pragma unroll
                        for (int i = 0; i < 4; i++) c1[m][nt][i] = 0.f;

                #pragma unroll
                for (int ks = 0; ks < 4; ks++) {
                    const int k0 = ks * 16 + 2 * q;
                    uint32_t aA[4], aB[4];
                    aA[0] = *(const uint32_t*)(arA + k0);
                    aA[1] = *(const uint32_t*)(arA + 8 * HSTR + k0);
                    aA[2] = *(const uint32_t*)(arA + k0 + 8);
                    aA[3] = *(const uint32_t*)(arA + 8 * HSTR + k0 + 8);
                    aB[0] = *(const uint32_t*)(arB + k0);
                    aB[1] = *(const uint32_t*)(arB + 8 * HSTR + k0);
                    aB[2] = *(const uint32_t*)(arB + k0 + 8);
                    aB[3] = *(const uint32_t*)(arB + 8 * HSTR + k0 + 8);
                    const uint2* bf = B2f + ks * 256 + half * 128 + lane;
                    #pragma unroll
                    for (int nt = 0; nt < 4; nt++) {
                        uint2 b = bf[nt * 32];
                        mma16(c1[0][nt], aA, b.x, b.y);
                        mma16(c1[1][nt], aB, b.x, b.y);
                    }
                }
                // bias + relu + pack: C-frags == A-frags for GEMM2
                #pragma unroll
                for (int kt = 0; kt < 2; kt++) {
                    const int ktg = half * 2 + kt;
                    const int cb = ktg * 16 + 2 * q;
                    const float bl0 = b2s[cb],     bl1 = b2s[cb + 1];
                    const float bh0 = b2s[cb + 8], bh1 = b2s[cb + 9];
                    #pragma unroll
                    for (int m = 0; m < 2; m++) {
                        a2[m][ktg][0] = h2pack(fmaxf(c1[m][2 * kt][0] + bl0, 0.f),
                                               fmaxf(c1[m][2 * kt][1] + bl1, 0.f));
                        a2[m][ktg][1] = h2pack(fmaxf(c1[m][2 * kt][2] + bl0, 0.f),
                                               fmaxf(c1[m][2 * kt][3] + bl1, 0.f));
                        a2[m][ktg][2] = h2pack(fmaxf(c1[m][2 * kt + 1][0] + bh0, 0.f),
                                               fmaxf(c1[m][2 * kt + 1][1] + bh1, 0.f));
                        a2[m][ktg][3] = h2pack(fmaxf(c1[m][2 * kt + 1][2] + bh0, 0.f),
                                               fmaxf(c1[m][2 * kt + 1][3] + bh1, 0.f));
                    }
                }
            }

            // GEMM2: both m-tiles share each B3 fragment
            float c2[2][4][4];
            #pragma unroll
            for (int m = 0; m < 2; m++)
                #pragma unroll
                for (int nt = 0; nt < 4; nt++)
                    #pragma unroll
                    for (int i = 0; i < 4; i++) c2[m][nt][i] = 0.f;

            #pragma unroll
            for (int kt = 0; kt < 4; kt++) {
                const uint2* bf = B3f + kt * 128 + lane;
                #pragma unroll
                for (int nt = 0; nt < 4; nt++) {
                    uint2 b = bf[nt * 32];
                    mma16(c2[0][nt], a2[0][kt], b.x, b.y);
                    mma16(c2[1][nt], a2[1][kt], b.x, b.y);
                }
            }
            #pragma unroll
            for (int nt = 0; nt < 4; nt++) {
                int cb = nt * 8 + 2 * q;
                *(float2*)(Yf + rA * YSTR + cb) = make_float2(c2[0][nt][0], c2[0][nt][1]);
                *(float2*)(Yf + (rA + 8) * YSTR + cb) = make_float2(c2[0][nt][2], c2[0][nt][3]);
                *(float2*)(Yf + rB * YSTR + cb) = make_float2(c2[1][nt][0], c2[1][nt][1]);
                *(float2*)(Yf + (rB + 8) * YSTR + cb) = make_float2(c2[1][nt][2], c2[1][nt][3]);
            }
        }
        ptok0 = tok0; pvtok = vtok;
        __syncthreads();   // Y ready; T0 free for next stage
    }

    // ---- tail: flush last stage's Y ----
    #pragma unroll 1
    for (int ti = 0; ti < 2; ti++) {
        int t = warp + ti * 8;
        if (t < pvtok) {
            const float* yc = Yf + (t * 17) * YSTR + lane;
            float y[17];
            #pragma unroll
            for (int j = 0; j < 17; j++) y[j] = yc[j * YSTR];
            float o[17];
            aggF(y, o);
            float* ob = out + ((size_t)(ptok0 + t) * 17) * 32 + lane;
            #pragma unroll
            for (int j = 0; j < 17; j++) ob[j * 32] = o[j] + b3r;
        }
    }
}

extern "C" void kernel_launch(void* const* d_in, const int* in_sizes, int n_in,
                              void* d_out, int out_size) {
    const float* x  = (const float*)d_in[0];
    const float* W1 = (const float*)d_in[1];
    const float* b1 = (const float*)d_in[2];
    const float* W2 = (const float*)d_in[3];
    const float* b2 = (const float*)d_in[4];
    const float* W3 = (const float*)d_in[5];
    const float* b3 = (const float*)d_in[6];
    float* out = (float*)d_out;

    const int NT = in_sizes[0] / (17 * 2);          // 65536 tokens
    const int nstages = (NT + TOKS - 1) / TOKS;     // 4370

    static int attr_done = 0;
    if (!attr_done) {
        cudaFuncSetAttribute(sge_h, cudaFuncAttributeMaxDynamicSharedMemorySize, SMEM_BYTES);
        attr_done = 1;
    }
    int grid = nstages < 296 ? nstages : 296;
    sge_h<<<grid, THREADS, SMEM_BYTES>>>(x, W1, b1, W2, b2, W3, b3, out, NT, nstages);
}